// round 3
// baseline (speedup 1.0000x reference)
#include <cuda_runtime.h>
#include <mma.h>
#include <cstdint>
#include <cstddef>

using namespace nvcuda;
namespace wx = nvcuda::wmma;

#define NB 256
#define HD 1024
#define DD 256
#define TT 128
#define KREC 2048      // [X_hi | X_lo] vs [W_hi | W_hi]
#define KFC  3072      // [hi | lo | hi] vs [W_hi | W_hi | W_lo]
#define LDH  3072      // row stride of g_hx
#define KT   32        // k-chunk (floats)
#define LDT  36        // smem tile row stride (32 + 4 pad)

// ---------------- static device scratch ----------------
__device__ float g_Wc2[4096 * KREC];            // [(Wih+Whh)_hi | same]  32 MB (gate-interleaved rows)
__device__ float g_Wp2[4096 * KREC];            // [Wih_hi | same]        32 MB
__device__ float g_Wfc3[DD * KFC];              // [Wfc_hi | Wfc_hi | Wfc_lo]
__device__ float g_x0[NB * KREC];               // [hT_hi | hT_lo]
__device__ float g_bp[4096];                    // permuted combined bias
__device__ float g_c[NB * HD];                  // cell state
__device__ float g_hx[(size_t)TT * NB * LDH];   // h history, split layout (384 MB)

__device__ __forceinline__ float sigm(float z) { return 1.0f / (1.0f + __expf(-z)); }

#define CP16(saddr, gptr) \
    asm volatile("cp.async.cg.shared.global [%0], [%1], 16;" :: "r"(saddr), "l"(gptr) : "memory")
#define CP_COMMIT() asm volatile("cp.async.commit_group;" ::: "memory")

// ---------------- prep: split/permute weights, biases, x0 ----------------
__global__ void prep_kernel(const float* __restrict__ Wih, const float* __restrict__ Whh,
                            const float* __restrict__ bih, const float* __restrict__ bhh,
                            const float* __restrict__ Wfc, const float* __restrict__ hT) {
    size_t idx = (size_t)blockIdx.x * 256 + threadIdx.x;
    if (idx < (size_t)4096 * HD) {
        int k = (int)(idx & (HD - 1));
        int rowp = (int)(idx >> 10);            // permuted gate row: j*4 + G
        int j = rowp >> 2, G = rowp & 3;
        size_t src = (size_t)(G * HD + j) * HD + k;
        float a = Wih[src];
        float s = a + Whh[src];
        float ahi = wx::__float_to_tf32(a);
        float shi = wx::__float_to_tf32(s);
        g_Wp2[(size_t)rowp * KREC + k] = ahi;
        g_Wp2[(size_t)rowp * KREC + HD + k] = ahi;
        g_Wc2[(size_t)rowp * KREC + k] = shi;
        g_Wc2[(size_t)rowp * KREC + HD + k] = shi;
    }
    if (idx < (size_t)DD * HD) {                // Wfc split (no permutation)
        int k = (int)(idx & (HD - 1));
        int r = (int)(idx >> 10);
        float w = Wfc[(size_t)r * HD + k];
        float whi = wx::__float_to_tf32(w);
        float wlo = wx::__float_to_tf32(w - whi);
        g_Wfc3[(size_t)r * KFC + k] = whi;
        g_Wfc3[(size_t)r * KFC + HD + k] = whi;
        g_Wfc3[(size_t)r * KFC + 2 * HD + k] = wlo;
    }
    if (idx < (size_t)NB * HD) {                // x0 split + zero cell state
        int k = (int)(idx & (HD - 1));
        int m = (int)(idx >> 10);
        float v = hT[(size_t)m * HD + k];
        float vhi = wx::__float_to_tf32(v);
        float vlo = wx::__float_to_tf32(v - vhi);
        g_x0[(size_t)m * KREC + k] = vhi;
        g_x0[(size_t)m * KREC + HD + k] = vlo;
        g_c[idx] = 0.0f;
    }
    if (idx < 4096) {                           // combined permuted bias
        int j = (int)(idx >> 2), G = (int)(idx & 3);
        g_bp[idx] = bih[G * HD + j] + bhh[G * HD + j];
    }
}

// ---------------- templated GEMM core (cp.async pipeline + wmma tf32) ----------
// Computes C[CTAM x CTAN] = A[m0: , :] @ B[n0: , :]^T (both K-major) into gates smem.
// Warp layout: NWM=2 x NWN=NWARP/2, warp tile 64 x 32 (4 m-frags x 2 n-frags of 16x16).
template<int CTAM, int CTAN, int NWARP>
__device__ __forceinline__ void gemm_core(
    const float* __restrict__ A, size_t lda, size_t m0,
    const float* __restrict__ B, size_t ldb, size_t n0,
    int nc, float* sm, float* gates, int ldg)
{
    constexpr int NTHR = NWARP * 32;
    constexpr int SSZ = (CTAM + CTAN) * LDT;    // floats per stage
    constexpr int NA = (CTAM * 8) / NTHR;       // cp16 per thread for A
    constexpr int NBT = (CTAN * 8) / NTHR;      // cp16 per thread for B
    const int tid = (int)threadIdx.x;
    const int w = tid >> 5;
    const int wm0 = (w & 1) * 64;
    const int wn0 = (w >> 1) * 32;

    wx::fragment<wx::accumulator, 16, 16, 8, float> cf[4][2];
#pragma unroll
    for (int i = 0; i < 4; ++i)
#pragma unroll
        for (int j = 0; j < 2; ++j) wx::fill_fragment(cf[i][j], 0.0f);

    auto load_chunk = [&](int kc) {
        int s = kc % 3;
        float* smA = sm + s * SSZ;
        float* smB = smA + CTAM * LDT;
        uint32_t sA = (uint32_t)__cvta_generic_to_shared(smA);
        uint32_t sB = (uint32_t)__cvta_generic_to_shared(smB);
        const float* gA = A + m0 * lda + (size_t)kc * KT;
        const float* gB = B + n0 * ldb + (size_t)kc * KT;
#pragma unroll
        for (int i = 0; i < NA; ++i) {
            int p = tid + i * NTHR;
            int r = p >> 3, sg = p & 7;
            CP16(sA + (uint32_t)(r * LDT + sg * 4) * 4u, gA + (size_t)r * lda + sg * 4);
        }
#pragma unroll
        for (int i = 0; i < NBT; ++i) {
            int p = tid + i * NTHR;
            int r = p >> 3, sg = p & 7;
            CP16(sB + (uint32_t)(r * LDT + sg * 4) * 4u, gB + (size_t)r * ldb + sg * 4);
        }
        CP_COMMIT();
    };

    load_chunk(0);
    load_chunk(1);

    for (int kc = 0; kc < nc; ++kc) {
        if (kc < nc - 1) asm volatile("cp.async.wait_group 1;" ::: "memory");
        else             asm volatile("cp.async.wait_group 0;" ::: "memory");
        __syncthreads();
        if (kc + 2 < nc) load_chunk(kc + 2);

        float* smA = sm + (kc % 3) * SSZ;
        float* smB = smA + CTAM * LDT;
#pragma unroll
        for (int ks = 0; ks < 4; ++ks) {
            wx::fragment<wx::matrix_a, 16, 16, 8, wx::precision::tf32, wx::row_major> af[4];
            wx::fragment<wx::matrix_b, 16, 16, 8, wx::precision::tf32, wx::col_major> bf[2];
#pragma unroll
            for (int i = 0; i < 4; ++i)
                wx::load_matrix_sync(af[i], smA + (wm0 + i * 16) * LDT + ks * 8, LDT);
#pragma unroll
            for (int j = 0; j < 2; ++j)
                wx::load_matrix_sync(bf[j], smB + (wn0 + j * 16) * LDT + ks * 8, LDT);
#pragma unroll
            for (int i = 0; i < 4; ++i)
#pragma unroll
                for (int j = 0; j < 2; ++j)
                    wx::mma_sync(cf[i][j], af[i], bf[j], cf[i][j]);
        }
    }

    __syncthreads();   // all warps done reading stages before aliasing as gates
#pragma unroll
    for (int i = 0; i < 4; ++i)
#pragma unroll
        for (int j = 0; j < 2; ++j)
            wx::store_matrix_sync(gates + (wm0 + i * 16) * ldg + wn0 + j * 16,
                                  cf[i][j], ldg, wx::mem_row_major);
    __syncthreads();
}

// ---------------- fused LSTM step ----------------
// grid (64, 2): n0 = bx*64 permuted gate-cols (16 hidden units), m0 = by*128 batch rows.
__global__ void __launch_bounds__(128) step_kernel(int t) {
    extern __shared__ float sm[];
    size_t n0 = (size_t)blockIdx.x * 64;
    size_t m0 = (size_t)blockIdx.y * 128;

    const float* A = (t == 0) ? g_x0 : (g_hx + (size_t)(t - 1) * NB * LDH);
    size_t lda = (t == 0) ? (size_t)KREC : (size_t)LDH;
    const float* B = (t == 0) ? g_Wp2 : g_Wc2;

    gemm_core<128, 64, 4>(A, lda, m0, B, KREC, n0, KREC / KT, sm, sm, 68);

    // pointwise epilogue from gates smem [128][68]
    const int tid = (int)threadIdx.x;
    const int ur = tid & 3;            // unit quad within 16 units
    const int rr = tid >> 2;           // 0..31
    const int j0 = (int)(n0 >> 2);     // global hidden-unit base

    float4 bq[4];
#pragma unroll
    for (int q = 0; q < 4; ++q)
        bq[q] = *(const float4*)(g_bp + n0 + (ur * 4 + q) * 4);

    float* hbase = g_hx + (size_t)t * NB * LDH;
#pragma unroll
    for (int p = 0; p < 4; ++p) {
        int r = rr + p * 32;
        size_t m = m0 + r;
        float4 cold = *(const float4*)(g_c + m * HD + j0 + ur * 4);
        float4 cnew, hhi, hlo;
        float* cn = &cnew.x; float* hh = &hhi.x; float* hl = &hlo.x;
        const float* co = &cold.x;
#pragma unroll
        for (int q = 0; q < 4; ++q) {
            float4 gv = *(const float4*)(sm + r * 68 + (ur * 4 + q) * 4);
            const float* bb = &bq[q].x;
            float iv = sigm(gv.x + bb[0]);
            float fv = sigm(gv.y + bb[1]);
            float gg = tanhf(gv.z + bb[2]);
            float ov = sigm(gv.w + bb[3]);
            float c = fmaf(fv, co[q], iv * gg);
            float h = ov * tanhf(c);
            cn[q] = c;
            float hi = wx::__float_to_tf32(h);
            hh[q] = hi;
            hl[q] = wx::__float_to_tf32(h - hi);
        }
        *(float4*)(g_c + m * HD + j0 + ur * 4) = cnew;
        float* hrow = hbase + m * LDH;
        *(float4*)(hrow + j0 + ur * 4)            = hhi;
        *(float4*)(hrow + HD + j0 + ur * 4)       = hlo;
        *(float4*)(hrow + 2 * HD + j0 + ur * 4)   = hhi;
    }
}

// ---------------- FC: out[32768, 256] = h @ Wfc^T + b (3-term tf32) ----------
// grid (2, 256): n0 = bx*128 out-cols, m0 = by*128 rows of g_hx.
__global__ void __launch_bounds__(256) fc_kernel(const float* __restrict__ bfc,
                                                 float* __restrict__ out) {
    extern __shared__ float sm[];
    size_t n0 = (size_t)blockIdx.x * 128;
    size_t m0 = (size_t)blockIdx.y * 128;

    gemm_core<128, 128, 8>(g_hx, LDH, m0, g_Wfc3, KFC, n0, KFC / KT, sm, sm, 132);

    const int tid = (int)threadIdx.x;
    const int cq = tid & 7;            // 16-col group
    const int rr = tid >> 3;           // 0..31
#pragma unroll
    for (int p = 0; p < 4; ++p) {
        int r = rr + p * 32;
        size_t m = m0 + r;
#pragma unroll
        for (int q = 0; q < 4; ++q) {
            int c = cq * 16 + q * 4;
            float4 gv = *(const float4*)(sm + r * 132 + c);
            float4 bv = *(const float4*)(bfc + n0 + c);
            gv.x += bv.x; gv.y += bv.y; gv.z += bv.z; gv.w += bv.w;
            *(float4*)(out + m * DD + n0 + c) = gv;
        }
    }
}

// ---------------- launch ----------------
extern "C" void kernel_launch(void* const* d_in, const int* in_sizes, int n_in,
                              void* d_out, int out_size) {
    const float* hT  = (const float*)d_in[0];
    // d_in[1] = t (int32) — fixed 128 for this problem
    const float* Wih = (const float*)d_in[2];
    const float* Whh = (const float*)d_in[3];
    const float* bih = (const float*)d_in[4];
    const float* bhh = (const float*)d_in[5];
    const float* Wfc = (const float*)d_in[6];
    const float* bfc = (const float*)d_in[7];
    float* out = (float*)d_out;

    const int STEP_SMEM = (128 + 64) * LDT * 4 * 3;    // 82944 B
    const int FC_SMEM   = (128 + 128) * LDT * 4 * 3;   // 110592 B
    cudaFuncSetAttribute(step_kernel, cudaFuncAttributeMaxDynamicSharedMemorySize, STEP_SMEM);
    cudaFuncSetAttribute(fc_kernel, cudaFuncAttributeMaxDynamicSharedMemorySize, FC_SMEM);

    prep_kernel<<<(4096 * HD) / 256, 256>>>(Wih, Whh, bih, bhh, Wfc, hT);

    dim3 sgrid(64, 2);
    for (int t = 0; t < TT; ++t)
        step_kernel<<<sgrid, 128, STEP_SMEM>>>(t);

    fc_kernel<<<dim3(2, 256), 256, FC_SMEM>>>(bfc, out);
}

// round 4
// speedup vs baseline: 5.3663x; 5.3663x over previous
#include <cuda_runtime.h>
#include <cuda_fp16.h>
#include <mma.h>
#include <cstdint>
#include <cstddef>

using namespace nvcuda;
namespace wx = nvcuda::wmma;

#define NB 256
#define HD 1024
#define DD 256
#define TT 128
#define KT 32              // k elems per chunk
#define NC (HD / KT)       // 32 chunks
#define LDTH 40            // smem tile row stride in halves (32 + 8 pad; 80B = 5*16B)
#define LDG 68             // gates smem row stride (floats)

// stage sizes (halves): A 128x40, B 64x40
#define STG_A (128 * LDTH)
#define STG_B (64 * LDTH)
#define STG_H (STG_A + STG_B)              // 7680 halves = 15360 B
#define DSMEM (3 * STG_H * 2)              // 46080 B (> gates 128*68*4 = 34816 B)

// ---------------- static device scratch ----------------
__device__ __half g_Wc[4096 * HD];              // gate-permuted (Wih+Whh)  8 MB
__device__ __half g_Wp[4096 * HD];              // gate-permuted Wih        8 MB
__device__ __half g_Wfc[DD * HD];               // Wfc fp16
__device__ __half g_x0[NB * HD];                // hT fp16
__device__ float  g_bp[4096];                   // permuted combined bias
__device__ float  g_c[NB * HD];                 // cell state fp32
__device__ __half g_h[(size_t)TT * NB * HD];    // hidden history fp16 (64 MB)

__device__ __forceinline__ float sigm(float z) { return 1.0f / (1.0f + __expf(-z)); }

#define CP16(saddr, gptr) \
    asm volatile("cp.async.cg.shared.global [%0], [%1], 16;" :: "r"(saddr), "l"(gptr) : "memory")
#define CP_COMMIT() asm volatile("cp.async.commit_group;" ::: "memory")

// ---------------- prep ----------------
// Permuted gate row' = j*4 + G (G in i,f,g,o) so one 64-col n-tile = 16 complete units.
__global__ void prep_kernel(const float* __restrict__ Wih, const float* __restrict__ Whh,
                            const float* __restrict__ bih, const float* __restrict__ bhh,
                            const float* __restrict__ Wfc, const float* __restrict__ hT) {
    size_t idx = (size_t)blockIdx.x * 256 + threadIdx.x;
    if (idx < (size_t)4096 * HD) {
        int k = (int)(idx & (HD - 1));
        int rowp = (int)(idx >> 10);
        int j = rowp >> 2, G = rowp & 3;
        size_t src = (size_t)(G * HD + j) * HD + k;
        float a = Wih[src];
        g_Wp[idx] = __float2half_rn(a);
        g_Wc[idx] = __float2half_rn(a + Whh[src]);
    }
    if (idx < (size_t)DD * HD) g_Wfc[idx] = __float2half_rn(Wfc[idx]);
    if (idx < (size_t)NB * HD) {
        g_x0[idx] = __float2half_rn(hT[idx]);
        g_c[idx] = 0.0f;
    }
    if (idx < 4096) {
        int j = (int)(idx >> 2), G = (int)(idx & 3);
        g_bp[idx] = bih[G * HD + j] + bhh[G * HD + j];
    }
}

// ---------------- fp16 GEMM core: C[128 x 64] = A[m0:,:] @ B[n0:,:]^T ----------------
// 256 threads = 8 warps, warp tile 32x32 (2x2 m16n16k16 frags), 3-stage cp.async pipeline.
// Result left in gates smem [128][LDG] (aliases the stage buffers).
__device__ __forceinline__ void gemm16(const __half* __restrict__ A, size_t m0,
                                       const __half* __restrict__ B, size_t n0,
                                       __half* smh, float* gates) {
    const int tid = (int)threadIdx.x;
    const int w = tid >> 5;
    const int wm0 = (w & 3) * 32;
    const int wn0 = (w >> 2) * 32;

    wx::fragment<wx::accumulator, 16, 16, 16, float> cf[2][2];
#pragma unroll
    for (int i = 0; i < 2; ++i)
#pragma unroll
        for (int j = 0; j < 2; ++j) wx::fill_fragment(cf[i][j], 0.0f);

    auto load_chunk = [&](int kc) {
        __half* smA = smh + (kc % 3) * STG_H;
        __half* smB = smA + STG_A;
        uint32_t sA = (uint32_t)__cvta_generic_to_shared(smA);
        uint32_t sB = (uint32_t)__cvta_generic_to_shared(smB);
        const __half* gA = A + m0 * HD + (size_t)kc * KT;
        const __half* gB = B + n0 * HD + (size_t)kc * KT;
#pragma unroll
        for (int i = 0; i < 2; ++i) {                  // A: 128 rows x 4 segs = 512 cp16
            int p = tid + i * 256;
            int r = p >> 2, seg = p & 3;
            CP16(sA + (uint32_t)(r * LDTH + seg * 8) * 2u, gA + (size_t)r * HD + seg * 8);
        }
        {                                              // B: 64 rows x 4 segs = 256 cp16
            int r = tid >> 2, seg = tid & 3;
            CP16(sB + (uint32_t)(r * LDTH + seg * 8) * 2u, gB + (size_t)r * HD + seg * 8);
        }
        CP_COMMIT();
    };

    load_chunk(0);
    load_chunk(1);

    for (int kc = 0; kc < NC; ++kc) {
        if (kc < NC - 1) asm volatile("cp.async.wait_group 1;" ::: "memory");
        else             asm volatile("cp.async.wait_group 0;" ::: "memory");
        __syncthreads();
        if (kc + 2 < NC) load_chunk(kc + 2);

        __half* smA = smh + (kc % 3) * STG_H;
        __half* smB = smA + STG_A;
#pragma unroll
        for (int ks = 0; ks < 2; ++ks) {
            wx::fragment<wx::matrix_a, 16, 16, 16, __half, wx::row_major> af[2];
            wx::fragment<wx::matrix_b, 16, 16, 16, __half, wx::col_major> bf[2];
#pragma unroll
            for (int i = 0; i < 2; ++i)
                wx::load_matrix_sync(af[i], smA + (wm0 + i * 16) * LDTH + ks * 16, LDTH);
#pragma unroll
            for (int j = 0; j < 2; ++j)
                wx::load_matrix_sync(bf[j], smB + (wn0 + j * 16) * LDTH + ks * 16, LDTH);
#pragma unroll
            for (int i = 0; i < 2; ++i)
#pragma unroll
                for (int j = 0; j < 2; ++j)
                    wx::mma_sync(cf[i][j], af[i], bf[j], cf[i][j]);
        }
    }

    __syncthreads();   // done reading stages; alias as gates
#pragma unroll
    for (int i = 0; i < 2; ++i)
#pragma unroll
        for (int j = 0; j < 2; ++j)
            wx::store_matrix_sync(gates + (wm0 + i * 16) * LDG + wn0 + j * 16,
                                  cf[i][j], LDG, wx::mem_row_major);
    __syncthreads();
}

// ---------------- fused LSTM step ----------------
// grid (64, 2): n0 = bx*64 permuted gate cols (16 units), m0 = by*128 batch rows
__global__ void __launch_bounds__(256) step_kernel(int t) {
    extern __shared__ __half smh[];
    float* gates = (float*)smh;
    size_t n0 = (size_t)blockIdx.x * 64;
    size_t m0 = (size_t)blockIdx.y * 128;

    const __half* A = (t == 0) ? g_x0 : (g_h + (size_t)(t - 1) * NB * HD);
    const __half* B = (t == 0) ? g_Wp : g_Wc;

    gemm16(A, m0, B, n0, smh, gates);

    // epilogue: 256 threads; thread -> unit-quad (tid&3) x row (tid>>2), 2 row passes
    const int tid = (int)threadIdx.x;
    const int ur = tid & 3;
    const int rr = tid >> 2;          // 0..63
    const int j0 = (int)(n0 >> 2);    // global hidden-unit base (16 units per tile)
    const bool first = (t == 0);

    float4 bq[4];
#pragma unroll
    for (int q = 0; q < 4; ++q)
        bq[q] = *(const float4*)(g_bp + n0 + (ur * 4 + q) * 4);

    __half* hbase = g_h + (size_t)t * NB * HD;
#pragma unroll
    for (int p = 0; p < 2; ++p) {
        int r = rr + p * 64;
        size_t m = m0 + r;
        float* cptr = g_c + m * HD + j0 + ur * 4;
        float4 cold = first ? make_float4(0.f, 0.f, 0.f, 0.f) : *(const float4*)cptr;
        const float* co = &cold.x;
        float4 cnew;
        float* cn = &cnew.x;
        __half hv[4];
#pragma unroll
        for (int q = 0; q < 4; ++q) {
            float4 gv = *(const float4*)(gates + r * LDG + (ur * 4 + q) * 4);
            const float* bb = &bq[q].x;
            float iv = sigm(gv.x + bb[0]);
            float fv = sigm(gv.y + bb[1]);
            float gg = tanhf(gv.z + bb[2]);
            float ov = sigm(gv.w + bb[3]);
            float c = fmaf(fv, co[q], iv * gg);
            cn[q] = c;
            hv[q] = __float2half_rn(ov * tanhf(c));
        }
        *(float4*)cptr = cnew;
        *(uint2*)(hbase + m * HD + j0 + ur * 4) = *(uint2*)hv;
    }
}

// ---------------- FC: out[32768, 256] = h @ Wfc^T + b ----------------
// grid (4, 256): n0 = bx*64 out cols, m0 = by*128 rows
__global__ void __launch_bounds__(256) fc_kernel(const float* __restrict__ bfc,
                                                 float* __restrict__ out) {
    extern __shared__ __half smh[];
    float* gates = (float*)smh;
    size_t n0 = (size_t)blockIdx.x * 64;
    size_t m0 = (size_t)blockIdx.y * 128;

    gemm16(g_h, m0, g_Wfc, n0, smh, gates);

    const int tid = (int)threadIdx.x;
    const int cg = tid & 3;
    const int rr = tid >> 2;
#pragma unroll
    for (int p = 0; p < 2; ++p) {
        int r = rr + p * 64;
        size_t m = m0 + r;
#pragma unroll
        for (int q = 0; q < 4; ++q) {
            int c = cg * 16 + q * 4;
            float4 gv = *(const float4*)(gates + r * LDG + c);
            float4 bv = *(const float4*)(bfc + n0 + c);
            gv.x += bv.x; gv.y += bv.y; gv.z += bv.z; gv.w += bv.w;
            *(float4*)(out + m * DD + n0 + c) = gv;
        }
    }
}

// ---------------- launch ----------------
extern "C" void kernel_launch(void* const* d_in, const int* in_sizes, int n_in,
                              void* d_out, int out_size) {
    const float* hT  = (const float*)d_in[0];
    // d_in[1] = t (int32) — fixed 128 for this problem
    const float* Wih = (const float*)d_in[2];
    const float* Whh = (const float*)d_in[3];
    const float* bih = (const float*)d_in[4];
    const float* bhh = (const float*)d_in[5];
    const float* Wfc = (const float*)d_in[6];
    const float* bfc = (const float*)d_in[7];
    float* out = (float*)d_out;

    cudaFuncSetAttribute(step_kernel, cudaFuncAttributeMaxDynamicSharedMemorySize, DSMEM);
    cudaFuncSetAttribute(fc_kernel, cudaFuncAttributeMaxDynamicSharedMemorySize, DSMEM);

    prep_kernel<<<(4096 * HD) / 256, 256>>>(Wih, Whh, bih, bhh, Wfc, hT);

    dim3 sgrid(64, 2);
    for (int t = 0; t < TT; ++t)
        step_kernel<<<sgrid, 256, DSMEM>>>(t);

    fc_kernel<<<dim3(4, 256), 256, DSMEM>>>(bfc, out);
}

// round 5
// speedup vs baseline: 6.8771x; 1.2815x over previous
#include <cuda_runtime.h>
#include <cuda_fp16.h>
#include <mma.h>
#include <cstdint>
#include <cstddef>

using namespace nvcuda;
namespace wx = nvcuda::wmma;

#define NB 256
#define HD 1024
#define DD 256
#define TT 128

// ---- persistent step kernel geometry ----
#define KT2 64                    // k per chunk
#define NCH (HD / KT2)            // 16 chunks
#define LDA 72                    // A smem row stride (halves): 64 + 8 pad
#define LDB 1032                  // B smem row stride (halves): 1024 + 8 pad
#define STGA (128 * LDA)          // halves per A stage (9216)
#define SMB_OFF (3 * STGA)        // B offset in halves
#define PERS_SMEM ((3 * STGA + 64 * LDB) * 2)   // 187392 B
#define LDG 68                    // gates smem row stride (floats); gates alias A stages (34.8KB < 55.3KB)

// ---- fc kernel geometry (from R4) ----
#define KT 32
#define NC (HD / KT)
#define LDTH 40
#define STG_A (128 * LDTH)
#define STG_B (64 * LDTH)
#define STG_H (STG_A + STG_B)
#define FC_SMEM (3 * STG_H * 2)

// ---------------- static device scratch ----------------
__device__ __half g_Wc[4096 * HD];              // gate-permuted (Wih+Whh)  8 MB
__device__ __half g_Wp[4096 * HD];              // gate-permuted Wih        8 MB
__device__ __half g_Wfc[DD * HD];
__device__ __half g_x0[NB * HD];
__device__ float  g_bp[4096];
__device__ __half g_h[(size_t)TT * NB * HD];    // hidden history fp16 (64 MB)

__device__ unsigned g_barcnt = 0;
__device__ volatile unsigned g_bargen = 0;

__device__ __forceinline__ float sigm(float z) { return 1.0f / (1.0f + __expf(-z)); }

#define CP16(saddr, gptr) \
    asm volatile("cp.async.cg.shared.global [%0], [%1], 16;" :: "r"(saddr), "l"(gptr) : "memory")
#define CP_COMMIT() asm volatile("cp.async.commit_group;" ::: "memory")

__device__ __forceinline__ void grid_barrier(unsigned nblk) {
    __syncthreads();
    if (threadIdx.x == 0) {
        __threadfence();                       // h stores visible before arrive
        unsigned g = g_bargen;
        if (atomicAdd(&g_barcnt, 1u) == nblk - 1) {
            g_barcnt = 0;
            __threadfence();
            g_bargen = g + 1;
        } else {
            while (g_bargen == g) { }
        }
    }
    __syncthreads();
}

// ---------------- prep ----------------
__global__ void prep_kernel(const float* __restrict__ Wih, const float* __restrict__ Whh,
                            const float* __restrict__ bih, const float* __restrict__ bhh,
                            const float* __restrict__ Wfc, const float* __restrict__ hT) {
    size_t idx = (size_t)blockIdx.x * 256 + threadIdx.x;
    if (idx < (size_t)4096 * HD) {
        int k = (int)(idx & (HD - 1));
        int rowp = (int)(idx >> 10);            // permuted gate row: j*4 + G
        int j = rowp >> 2, G = rowp & 3;
        size_t src = (size_t)(G * HD + j) * HD + k;
        float a = Wih[src];
        g_Wp[idx] = __float2half_rn(a);
        g_Wc[idx] = __float2half_rn(a + Whh[src]);
    }
    if (idx < (size_t)DD * HD) g_Wfc[idx] = __float2half_rn(Wfc[idx]);
    if (idx < (size_t)NB * HD) g_x0[idx] = __float2half_rn(hT[idx]);
    if (idx < 4096) {
        int j = (int)(idx >> 2), G = (int)(idx & 3);
        g_bp[idx] = bih[G * HD + j] + bhh[G * HD + j];
    }
}

// ---------------- persistent LSTM: all 128 steps in one kernel ----------------
// grid (64, 2): n0 = bx*64 permuted gate cols (16 units), m0 = by*128 batch rows.
// B tile (64x1024 fp16) resident in smem; c state in registers; grid barrier per step.
__global__ void __launch_bounds__(256) lstm_persist() {
    extern __shared__ __half smh[];
    __half* smB = smh + SMB_OFF;
    float* gates = (float*)smh;                 // aliases A stages between steps

    const int tid = (int)threadIdx.x;
    const int w = tid >> 5;
    const int wm0 = (w & 3) * 32;
    const int wn0 = (w >> 2) * 32;
    const size_t n0 = (size_t)blockIdx.x * 64;
    const size_t m0 = (size_t)blockIdx.y * 128;
    const unsigned nblk = gridDim.x * gridDim.y;

    const int ur = tid & 3;                     // epilogue: unit quad
    const int rr = tid >> 2;                    // epilogue: row 0..63
    const int j0 = (int)(n0 >> 2);              // global hidden-unit base

    // resident B load (32 cp16 per thread)
    auto loadB = [&](const __half* __restrict__ Wsrc) {
        uint32_t sB = (uint32_t)__cvta_generic_to_shared(smB);
#pragma unroll
        for (int i = 0; i < 32; ++i) {
            int p = tid + i * 256;              // 0..8191
            int r = p >> 7;                     // row 0..63
            int sg = p & 127;                   // 128 segs of 8 halves
            CP16(sB + (uint32_t)(r * LDB + sg * 8) * 2u, Wsrc + (n0 + (size_t)r) * HD + sg * 8);
        }
        CP_COMMIT();
    };

    loadB(g_Wp);                                // step-0 weights
    asm volatile("cp.async.wait_group 0;" ::: "memory");
    __syncthreads();

    // biases: constant across steps
    float4 bq[4];
#pragma unroll
    for (int q = 0; q < 4; ++q)
        bq[q] = *(const float4*)(g_bp + n0 + (ur * 4 + q) * 4);

    // cell state in registers (init 0 == c_{-1})
    float creg[8];
#pragma unroll
    for (int i = 0; i < 8; ++i) creg[i] = 0.0f;

    for (int t = 0; t < TT; ++t) {
        const __half* A = (t == 0) ? g_x0 : (g_h + (size_t)(t - 1) * NB * HD);

        auto loadA = [&](int kc) {
            uint32_t sA = (uint32_t)__cvta_generic_to_shared(smh + (kc % 3) * STGA);
            const __half* gA = A + m0 * HD + (size_t)kc * KT2;
#pragma unroll
            for (int i = 0; i < 4; ++i) {
                int p = tid + i * 256;          // 0..1023
                int r = p >> 3;                 // 0..127
                int sg = p & 7;                 // 8 segs of 8 halves
                CP16(sA + (uint32_t)(r * LDA + sg * 8) * 2u, gA + (size_t)r * HD + sg * 8);
            }
            CP_COMMIT();
        };

        wx::fragment<wx::accumulator, 16, 16, 16, float> cf[2][2];
#pragma unroll
        for (int i = 0; i < 2; ++i)
#pragma unroll
            for (int j = 0; j < 2; ++j) wx::fill_fragment(cf[i][j], 0.0f);

        loadA(0);
        loadA(1);

        for (int kc = 0; kc < NCH; ++kc) {
            if (kc < NCH - 1) asm volatile("cp.async.wait_group 1;" ::: "memory");
            else              asm volatile("cp.async.wait_group 0;" ::: "memory");
            __syncthreads();
            if (kc + 2 < NCH) loadA(kc + 2);

            const __half* smA = smh + (kc % 3) * STGA;
#pragma unroll
            for (int ks = 0; ks < 4; ++ks) {
                wx::fragment<wx::matrix_a, 16, 16, 16, __half, wx::row_major> af[2];
                wx::fragment<wx::matrix_b, 16, 16, 16, __half, wx::col_major> bf[2];
#pragma unroll
                for (int i = 0; i < 2; ++i)
                    wx::load_matrix_sync(af[i], smA + (wm0 + i * 16) * LDA + ks * 16, LDA);
#pragma unroll
                for (int j = 0; j < 2; ++j)
                    wx::load_matrix_sync(bf[j], smB + (wn0 + j * 16) * LDB + kc * KT2 + ks * 16, LDB);
#pragma unroll
                for (int i = 0; i < 2; ++i)
#pragma unroll
                    for (int j = 0; j < 2; ++j)
                        wx::mma_sync(cf[i][j], af[i], bf[j], cf[i][j]);
            }
        }

        __syncthreads();     // A stages free; alias as gates
#pragma unroll
        for (int i = 0; i < 2; ++i)
#pragma unroll
            for (int j = 0; j < 2; ++j)
                wx::store_matrix_sync(gates + (wm0 + i * 16) * LDG + wn0 + j * 16,
                                      cf[i][j], LDG, wx::mem_row_major);
        __syncthreads();

        // swap in combined weights after step 0 (MMA for step 0 is done; overlaps epilogue)
        if (t == 0) loadB(g_Wc);

        // pointwise epilogue; c stays in registers
        __half* hbase = g_h + (size_t)t * NB * HD;
#pragma unroll
        for (int p = 0; p < 2; ++p) {
            int r = rr + p * 64;
            size_t m = m0 + r;
            __half hv[4];
#pragma unroll
            for (int q = 0; q < 4; ++q) {
                float4 gv = *(const float4*)(gates + r * LDG + (ur * 4 + q) * 4);
                const float* bb = &bq[q].x;
                float iv = sigm(gv.x + bb[0]);
                float fv = sigm(gv.y + bb[1]);
                float gg = tanhf(gv.z + bb[2]);
                float ov = sigm(gv.w + bb[3]);
                float c = fmaf(fv, creg[p * 4 + q], iv * gg);
                creg[p * 4 + q] = c;
                hv[q] = __float2half_rn(ov * tanhf(c));
            }
            *(uint2*)(hbase + m * HD + j0 + ur * 4) = *(uint2*)hv;
        }

        if (t == 0) {
            asm volatile("cp.async.wait_group 0;" ::: "memory");
        }
        grid_barrier(nblk);   // h[t] visible to all CTAs; also covers B swap
    }
}

// ---------------- FC (R4, unchanged): out[32768,256] = h @ Wfc^T + b ----------
__device__ __forceinline__ void gemm16_fc(const __half* __restrict__ A, size_t m0,
                                          const __half* __restrict__ B, size_t n0,
                                          __half* smh, float* gates) {
    const int tid = (int)threadIdx.x;
    const int w = tid >> 5;
    const int wm0 = (w & 3) * 32;
    const int wn0 = (w >> 2) * 32;

    wx::fragment<wx::accumulator, 16, 16, 16, float> cf[2][2];
#pragma unroll
    for (int i = 0; i < 2; ++i)
#pragma unroll
        for (int j = 0; j < 2; ++j) wx::fill_fragment(cf[i][j], 0.0f);

    auto load_chunk = [&](int kc) {
        __half* smA = smh + (kc % 3) * STG_H;
        __half* smB = smA + STG_A;
        uint32_t sA = (uint32_t)__cvta_generic_to_shared(smA);
        uint32_t sB = (uint32_t)__cvta_generic_to_shared(smB);
        const __half* gA = A + m0 * HD + (size_t)kc * KT;
        const __half* gB = B + n0 * HD + (size_t)kc * KT;
#pragma unroll
        for (int i = 0; i < 2; ++i) {
            int p = tid + i * 256;
            int r = p >> 2, seg = p & 3;
            CP16(sA + (uint32_t)(r * LDTH + seg * 8) * 2u, gA + (size_t)r * HD + seg * 8);
        }
        {
            int r = tid >> 2, seg = tid & 3;
            CP16(sB + (uint32_t)(r * LDTH + seg * 8) * 2u, gB + (size_t)r * HD + seg * 8);
        }
        CP_COMMIT();
    };

    load_chunk(0);
    load_chunk(1);

    for (int kc = 0; kc < NC; ++kc) {
        if (kc < NC - 1) asm volatile("cp.async.wait_group 1;" ::: "memory");
        else             asm volatile("cp.async.wait_group 0;" ::: "memory");
        __syncthreads();
        if (kc + 2 < NC) load_chunk(kc + 2);

        __half* smA = smh + (kc % 3) * STG_H;
        __half* smB = smA + STG_A;
#pragma unroll
        for (int ks = 0; ks < 2; ++ks) {
            wx::fragment<wx::matrix_a, 16, 16, 16, __half, wx::row_major> af[2];
            wx::fragment<wx::matrix_b, 16, 16, 16, __half, wx::col_major> bf[2];
#pragma unroll
            for (int i = 0; i < 2; ++i)
                wx::load_matrix_sync(af[i], smA + (wm0 + i * 16) * LDTH + ks * 16, LDTH);
#pragma unroll
            for (int j = 0; j < 2; ++j)
                wx::load_matrix_sync(bf[j], smB + (wn0 + j * 16) * LDTH + ks * 16, LDTH);
#pragma unroll
            for (int i = 0; i < 2; ++i)
#pragma unroll
                for (int j = 0; j < 2; ++j)
                    wx::mma_sync(cf[i][j], af[i], bf[j], cf[i][j]);
        }
    }

    __syncthreads();
#pragma unroll
    for (int i = 0; i < 2; ++i)
#pragma unroll
        for (int j = 0; j < 2; ++j)
            wx::store_matrix_sync(gates + (wm0 + i * 16) * LDG + wn0 + j * 16,
                                  cf[i][j], LDG, wx::mem_row_major);
    __syncthreads();
}

__global__ void __launch_bounds__(256) fc_kernel(const float* __restrict__ bfc,
                                                 float* __restrict__ out) {
    extern __shared__ __half smh[];
    float* gates = (float*)smh;
    size_t n0 = (size_t)blockIdx.x * 64;
    size_t m0 = (size_t)blockIdx.y * 128;

    gemm16_fc(g_h, m0, g_Wfc, n0, smh, gates);

    const int tid = (int)threadIdx.x;
    const int cg = tid & 3;
    const int rr = tid >> 2;
#pragma unroll
    for (int p = 0; p < 2; ++p) {
        int r = rr + p * 64;
        size_t m = m0 + r;
#pragma unroll
        for (int q = 0; q < 4; ++q) {
            int c = cg * 16 + q * 4;
            float4 gv = *(const float4*)(gates + r * LDG + c);
            float4 bv = *(const float4*)(bfc + n0 + c);
            gv.x += bv.x; gv.y += bv.y; gv.z += bv.z; gv.w += bv.w;
            *(float4*)(out + m * DD + n0 + c) = gv;
        }
    }
}

// ---------------- launch ----------------
extern "C" void kernel_launch(void* const* d_in, const int* in_sizes, int n_in,
                              void* d_out, int out_size) {
    const float* hT  = (const float*)d_in[0];
    // d_in[1] = t (int32) — fixed 128 for this problem
    const float* Wih = (const float*)d_in[2];
    const float* Whh = (const float*)d_in[3];
    const float* bih = (const float*)d_in[4];
    const float* bhh = (const float*)d_in[5];
    const float* Wfc = (const float*)d_in[6];
    const float* bfc = (const float*)d_in[7];
    float* out = (float*)d_out;

    cudaFuncSetAttribute(lstm_persist, cudaFuncAttributeMaxDynamicSharedMemorySize, PERS_SMEM);
    cudaFuncSetAttribute(fc_kernel, cudaFuncAttributeMaxDynamicSharedMemorySize, FC_SMEM);

    prep_kernel<<<(4096 * HD) / 256, 256>>>(Wih, Whh, bih, bhh, Wfc, hT);

    lstm_persist<<<dim3(64, 2), 256, PERS_SMEM>>>();

    fc_kernel<<<dim3(4, 256), 256, FC_SMEM>>>(bfc, out);
}